// round 1
// baseline (speedup 1.0000x reference)
#include <cuda_runtime.h>
#include <math.h>

// ---- Problem constants ----
#define BDIM 2048
#define DDIM 1024
#define UDIM 1024
#define LNUM 3
#define NB   8                 // NUM_BASIS = GRID_SIZE + SPLINE_ORDER = 5+3
#define KACT (DDIM + DDIM*NB)  // 9216
#define NCOMB (UDIM + LNUM*UDIM) // 4096

// ---- Scratch (device globals: no allocation allowed) ----
__device__ float g_z[BDIM * 4 * UDIM];    // LSTM pre-activations  [2048,4096]
__device__ float g_act[BDIM * KACT];      // [silu(x), bases]      [2048,9216]
__device__ float g_comb[BDIM * NCOMB];    // [h, kan0, kan1, kan2] [2048,4096]

// =====================================================================
// Generic split-K GEMM: C[m, colOff+n] = sum_k A(m,k)*W(k,n) (+bias[n])
//  A(m,k): k <  Ksplit -> A0[m*lda0 + k]
//          k >= Ksplit -> A1[m*lda1 + (k-Ksplit)]
//  W(k,n): k <  Ksplit -> W0[k*ldw + n]
//          k >= Ksplit -> W1[(k-Ksplit)*ldw + n]
// All dims must divide tile sizes (they do for this problem).
// BM=128, BN=128, BK=8, 256 threads, 8x8 per-thread microtile.
// =====================================================================
__global__ __launch_bounds__(256) void gemm_splitk(
    const float* __restrict__ A0, int lda0,
    const float* __restrict__ A1, int lda1,
    const float* __restrict__ W0, const float* __restrict__ W1, int ldw,
    const float* __restrict__ bias,
    float* __restrict__ C, int ldc, int colOff,
    int K, int Ksplit)
{
    const int BM = 128, BN = 128, BK = 8;
    __shared__ float As[BK][BM];
    __shared__ float Bs[BK][BN];

    const int tid = threadIdx.x;
    const int rowBase = blockIdx.y * BM;
    const int colBase = blockIdx.x * BN;

    const int tx = tid & 15;       // 0..15 -> col microtile
    const int ty = tid >> 4;       // 0..15 -> row microtile

    // A-tile loader: 128 rows x 8 cols -> one float4 per thread
    const int aRow = tid >> 1;         // 0..127
    const int aCol = (tid & 1) * 4;    // 0 or 4
    // B-tile loader: 8 rows x 128 cols -> one float4 per thread
    const int bRow = tid >> 5;         // 0..7
    const int bCol = (tid & 31) * 4;   // 0..124

    float acc[8][8];
#pragma unroll
    for (int i = 0; i < 8; i++)
#pragma unroll
        for (int j = 0; j < 8; j++) acc[i][j] = 0.0f;

    for (int k0 = 0; k0 < K; k0 += BK) {
        const float* Ap; int lda, ka;
        const float* Wp; int kw;
        if (k0 < Ksplit) { Ap = A0; lda = lda0; ka = k0;          Wp = W0; kw = k0; }
        else             { Ap = A1; lda = lda1; ka = k0 - Ksplit; Wp = W1; kw = k0 - Ksplit; }

        float4 av = *(const float4*)(Ap + (size_t)(rowBase + aRow) * lda + ka + aCol);
        As[aCol + 0][aRow] = av.x;
        As[aCol + 1][aRow] = av.y;
        As[aCol + 2][aRow] = av.z;
        As[aCol + 3][aRow] = av.w;

        float4 bv = *(const float4*)(Wp + (size_t)(kw + bRow) * ldw + colBase + bCol);
        *(float4*)&Bs[bRow][bCol] = bv;

        __syncthreads();

#pragma unroll
        for (int k = 0; k < BK; k++) {
            float a[8], b[8];
            *(float4*)&a[0] = *(const float4*)&As[k][ty * 8];
            *(float4*)&a[4] = *(const float4*)&As[k][ty * 8 + 4];
            *(float4*)&b[0] = *(const float4*)&Bs[k][tx * 8];
            *(float4*)&b[4] = *(const float4*)&Bs[k][tx * 8 + 4];
#pragma unroll
            for (int i = 0; i < 8; i++)
#pragma unroll
                for (int j = 0; j < 8; j++)
                    acc[i][j] = fmaf(a[i], b[j], acc[i][j]);
        }
        __syncthreads();
    }

#pragma unroll
    for (int i = 0; i < 8; i++) {
        const int r = rowBase + ty * 8 + i;
#pragma unroll
        for (int j = 0; j < 8; j += 4) {
            const int c = colBase + tx * 8 + j;
            float4 v;
            v.x = acc[i][j + 0];
            v.y = acc[i][j + 1];
            v.z = acc[i][j + 2];
            v.w = acc[i][j + 3];
            if (bias) {
                v.x += bias[c + 0]; v.y += bias[c + 1];
                v.z += bias[c + 2]; v.w += bias[c + 3];
            }
            *(float4*)(C + (size_t)r * ldc + colOff + c) = v;
        }
    }
}

// =====================================================================
// LSTM gates: z -> (h, c). Keras order i,f,g,o.
// Writes h to d_out[B*U..), c to d_out[2*B*U..), and h into g_comb[:,0:U].
// =====================================================================
__global__ void lstm_gates_kernel(const float* __restrict__ z,
                                  const float* __restrict__ c_prev,
                                  float* __restrict__ out_h,
                                  float* __restrict__ out_c,
                                  float* __restrict__ comb)
{
    int i = blockIdx.x * blockDim.x + threadIdx.x;
    if (i >= BDIM * UDIM) return;
    int b = i / UDIM, u = i - b * UDIM;
    const float* zr = z + (size_t)b * 4 * UDIM;
    float zi = zr[u];
    float zf = zr[UDIM + u];
    float zg = zr[2 * UDIM + u];
    float zo = zr[3 * UDIM + u];
    float si = 1.0f / (1.0f + expf(-zi));
    float sf = 1.0f / (1.0f + expf(-zf));
    float so = 1.0f / (1.0f + expf(-zo));
    float c = sf * c_prev[i] + si * tanhf(zg);
    float h = so * tanhf(c);
    out_h[i] = h;
    out_c[i] = c;
    comb[(size_t)b * NCOMB + u] = h;
}

// =====================================================================
// Activation builder: silu(x) and cubic B-spline bases (Cox-de Boor).
// Knots: t_j = -1 + 0.4*(j-3), j=0..11 (12 knots, uniform).
// =====================================================================
__device__ __forceinline__ float knot(int j) {
    return (float)(-1.0 + (2.0 / 5.0) * (double)(j - 3));
}

__global__ void act_kernel(const float* __restrict__ x, float* __restrict__ act)
{
    int i = blockIdx.x * blockDim.x + threadIdx.x;
    if (i >= BDIM * DDIM) return;
    int b = i / DDIM, d = i - b * DDIM;
    float xv = x[i];
    float s = xv / (1.0f + expf(-xv));   // silu

    float bb[11];
#pragma unroll
    for (int j = 0; j < 11; j++)
        bb[j] = (xv >= knot(j) && xv < knot(j + 1)) ? 1.0f : 0.0f;
#pragma unroll
    for (int p = 1; p <= 3; p++) {
#pragma unroll
        for (int j = 0; j <= 10 - p; j++) {
            float tj  = knot(j),     tjp  = knot(j + p);
            float tj1 = knot(j + 1), tjp1 = knot(j + p + 1);
            float left  = (xv - tj)   / (tjp  - tj)  * bb[j];
            float right = (tjp1 - xv) / (tjp1 - tj1) * bb[j + 1];
            bb[j] = left + right;
        }
    }

    float* row = act + (size_t)b * KACT;
    row[d] = s;
    float* sp = row + DDIM + d * NB;   // 32B-aligned (d*8 floats)
    float4 v0, v1;
    v0.x = bb[0]; v0.y = bb[1]; v0.z = bb[2]; v0.w = bb[3];
    v1.x = bb[4]; v1.y = bb[5]; v1.z = bb[6]; v1.w = bb[7];
    *(float4*)(sp + 0) = v0;
    *(float4*)(sp + 4) = v1;
}

// =====================================================================
// Launch
// =====================================================================
extern "C" void kernel_launch(void* const* d_in, const int* in_sizes, int n_in,
                              void* d_out, int out_size)
{
    const float* x        = (const float*)d_in[0];   // [2048,1024]
    const float* h_prev   = (const float*)d_in[1];   // [2048,1024]
    const float* c_prev   = (const float*)d_in[2];   // [2048,1024]
    const float* lstm_k   = (const float*)d_in[3];   // [1024,4096]
    const float* lstm_rk  = (const float*)d_in[4];   // [1024,4096]
    const float* lstm_b   = (const float*)d_in[5];   // [4096]
    const float* kan_bw   = (const float*)d_in[6];   // [3,1024,1024]
    const float* kan_sw   = (const float*)d_in[7];   // [3,8192,1024]
    const float* comb_w   = (const float*)d_in[8];   // [4096,1024]
    const float* comb_b   = (const float*)d_in[9];   // [1024]

    float* out    = (float*)d_out;                    // [output | h | c]
    float* out_h  = out + (size_t)BDIM * UDIM;
    float* out_c  = out + (size_t)2 * BDIM * UDIM;

    float* z    = nullptr; cudaGetSymbolAddress((void**)&z,    g_z);
    float* act  = nullptr; cudaGetSymbolAddress((void**)&act,  g_act);
    float* comb = nullptr; cudaGetSymbolAddress((void**)&comb, g_comb);

    dim3 blk(256);

    // 1) LSTM pre-activations: z = x@Wk + h_prev@Wr + b   [2048,4096], K=2048 split at 1024
    {
        dim3 grid(4096 / 128, BDIM / 128);
        gemm_splitk<<<grid, blk>>>(x, DDIM, h_prev, UDIM,
                                   lstm_k, lstm_rk, 4096,
                                   lstm_b, z, 4096, 0,
                                   2048, 1024);
    }

    // 2) Gates -> h, c (also h into comb[:,0:1024])
    {
        int n = BDIM * UDIM;
        lstm_gates_kernel<<<(n + 255) / 256, 256>>>(z, c_prev, out_h, out_c, comb);
    }

    // 3) Activations: [silu(x), bases] -> g_act [2048, 9216]
    {
        int n = BDIM * DDIM;
        act_kernel<<<(n + 255) / 256, 256>>>(x, act);
    }

    // 4) KAN layers: act @ [base_w_l ; spline_w_l] -> comb[:, 1024 + l*1024 ...]
    for (int l = 0; l < LNUM; l++) {
        dim3 grid(UDIM / 128, BDIM / 128);
        const float* W0 = kan_bw + (size_t)l * DDIM * UDIM;
        const float* W1 = kan_sw + (size_t)l * DDIM * NB * UDIM;
        gemm_splitk<<<grid, blk>>>(act, KACT, act + DDIM, KACT,
                                   W0, W1, UDIM,
                                   nullptr, comb, NCOMB, UDIM + l * UDIM,
                                   KACT, DDIM);
    }

    // 5) Combine: comb @ combine_w + combine_b -> output
    {
        dim3 grid(UDIM / 128, BDIM / 128);
        gemm_splitk<<<grid, blk>>>(comb, NCOMB, comb, NCOMB,
                                   comb_w, comb_w, UDIM,
                                   comb_b, out, UDIM, 0,
                                   NCOMB, NCOMB);
    }
}

// round 3
// speedup vs baseline: 5.1728x; 5.1728x over previous
#include <cuda_runtime.h>
#include <cstdint>
#include <math.h>

// ---- Problem constants ----
#define BDIM 2048
#define DDIM 1024
#define UDIM 1024
#define NB   8
#define KACT 9216              // 1024 + 1024*8
#define NCOMB 4096             // 1024 + 3*1024

// ---- Scratch (device globals; no allocation allowed) ----
__device__ float g_xh[BDIM * 2048];            // [x | h_prev] (tf32-rounded)
__device__ float g_z[BDIM * 4096];             // LSTM preacts (full fp32)
__device__ float g_act[(size_t)BDIM * KACT];   // [silu(x) | bases] (tf32-rounded)
__device__ float g_comb[BDIM * NCOMB];         // [h | kan0..2] (tf32-rounded)

// ---- helpers ----
__device__ __forceinline__ float tf32f(float f) {
    float o; asm("cvt.rna.tf32.f32 %0, %1;" : "=f"(o) : "f"(f)); return o;
}
__device__ __forceinline__ uint32_t tf32u(uint32_t b) {
    uint32_t o; asm("cvt.rna.tf32.f32 %0, %1;" : "=r"(o) : "r"(b)); return o;
}
__device__ __forceinline__ uint32_t smem_u32(const void* p) {
    uint32_t a;
    asm("{ .reg .u64 t; cvta.to.shared.u64 t, %1; cvt.u32.u64 %0, t; }"
        : "=r"(a) : "l"(p));
    return a;
}
__device__ __forceinline__ void cp16(uint32_t s, const void* g) {
    asm volatile("cp.async.cg.shared.global [%0], [%1], 16;" :: "r"(s), "l"(g));
}
__device__ __forceinline__ void cp_commit() {
    asm volatile("cp.async.commit_group;" ::: "memory");
}
template<int N> __device__ __forceinline__ void cp_wait() {
    asm volatile("cp.async.wait_group %0;" :: "n"(N) : "memory");
}
__device__ __forceinline__ void mma8(float* c, const uint32_t* a, const uint32_t* b) {
    asm volatile(
        "mma.sync.aligned.m16n8k8.row.col.f32.tf32.tf32.f32 "
        "{%0,%1,%2,%3}, {%4,%5,%6,%7}, {%8,%9}, {%0,%1,%2,%3};"
        : "+f"(c[0]), "+f"(c[1]), "+f"(c[2]), "+f"(c[3])
        : "r"(a[0]), "r"(a[1]), "r"(a[2]), "r"(a[3]), "r"(b[0]), "r"(b[1]));
}

// =====================================================================
// TF32 mma.sync GEMM
//  C[m, colOff+colBase+n] = sum_k A[m,k] * B(k, colBase+n)  (+bias)
//  B(k, col): l = colBase/nPerL, colRem = colBase%nPerL
//             k <  ksplit -> B0[l*bz0 + k*ldb + colRem + n]
//             k >= ksplit -> B1[l*bz1 + (k-ksplit)*ldb + colRem + n]
//  BM=128, BN=128, BK=16, 4-stage cp.async, 8 warps (2x4), 64x32/warp.
// =====================================================================
#define BM 128
#define BN 128
#define BK 16
#define SSTG 4
#define ASTR 20                 // A smem row stride (floats), conflict-free
#define BSTR 136                // B smem row stride (floats), conflict-free
#define ABYTES (BM * ASTR * 4)  // 10240
#define BBYTES (BK * BSTR * 4)  // 8704
#define STGB (ABYTES + BBYTES)  // 18944

extern __shared__ char smem_raw[];

__global__ __launch_bounds__(256, 2) void gemm_mma(
    const float* __restrict__ A, int lda,
    const float* __restrict__ B0, long bz0,
    const float* __restrict__ B1, long bz1,
    int ldb, int nPerL, int ksplit,
    const float* __restrict__ bias,
    float* __restrict__ C, int ldc, int colOff,
    int K, int cvtOut)
{
    const int tid = threadIdx.x;
    const int rowBase = blockIdx.y * BM;
    const int colBase = blockIdx.x * BN;
    const int l = colBase / nPerL;
    const int colRem = colBase - l * nPerL;
    const float* Bp0 = B0 + (size_t)l * bz0 + colRem;
    const float* Bp1 = B1 + (size_t)l * bz1 + colRem;
    const float* Ap  = A + (size_t)rowBase * lda;

    const uint32_t sb = smem_u32(smem_raw);

    // loader coords
    const int a_r = tid >> 1;                 // A: idx = i*256+tid; r=idx>>2 via i
    const int b_r = tid >> 5;                 // unused directly; computed per i

    float acc[4][4][4];
#pragma unroll
    for (int i = 0; i < 4; i++)
#pragma unroll
        for (int j = 0; j < 4; j++)
#pragma unroll
            for (int q = 0; q < 4; q++) acc[i][j][q] = 0.0f;

    (void)a_r; (void)b_r;

    const int nk = K / BK;

    // stage loader
    auto load_stage = [&](int t, int s) {
        const int kBase = t * BK;
        // A tile: 128 rows x 16 floats = 512 float4
#pragma unroll
        for (int i = 0; i < 2; i++) {
            int idx = i * 256 + tid;
            int r = idx >> 2, c = (idx & 3) * 4;
            cp16(sb + s * STGB + (r * ASTR + c) * 4,
                 Ap + (size_t)r * lda + kBase + c);
        }
        // B tile: 16 rows x 128 floats = 512 float4
#pragma unroll
        for (int i = 0; i < 2; i++) {
            int idx = i * 256 + tid;
            int r = idx >> 5, c = (idx & 31) * 4;
            int kg = kBase + r;
            const float* src = (kg < ksplit)
                ? Bp0 + (size_t)kg * ldb + c
                : Bp1 + (size_t)(kg - ksplit) * ldb + c;
            cp16(sb + s * STGB + ABYTES + (r * BSTR + c) * 4, src);
        }
    };

    // prologue
#pragma unroll
    for (int s = 0; s < SSTG - 1; s++) { load_stage(s, s); cp_commit(); }

    const int lane = tid & 31;
    const int w = tid >> 5;
    const int wm = (w >> 2) * 64;       // warp row offset within CTA tile
    const int wn = (w & 3) * 32;        // warp col offset
    const int gid = lane >> 2;
    const int tg  = lane & 3;

    for (int t = 0; t < nk; t++) {
        cp_wait<SSTG - 2>();
        __syncthreads();
        const int tn = t + SSTG - 1;
        if (tn < nk) load_stage(tn, tn % SSTG);
        cp_commit();   // unconditional: keeps group accounting exact in the tail

        const uint32_t* sA = (const uint32_t*)(smem_raw + (t % SSTG) * STGB);
        const uint32_t* sB = (const uint32_t*)(smem_raw + (t % SSTG) * STGB + ABYTES);

#pragma unroll
        for (int ks = 0; ks < 2; ks++) {
            uint32_t af[4][4], bf[4][2];
#pragma unroll
            for (int i = 0; i < 4; i++) {
                const uint32_t* p = sA + (wm + i * 16 + gid) * ASTR + ks * 8 + tg;
                af[i][0] = p[0];
                af[i][1] = p[8 * ASTR];
                af[i][2] = p[4];
                af[i][3] = p[8 * ASTR + 4];
            }
#pragma unroll
            for (int j = 0; j < 4; j++) {
                const uint32_t* p = sB + (ks * 8 + tg) * BSTR + wn + j * 8 + gid;
                bf[j][0] = tf32u(p[0]);
                bf[j][1] = tf32u(p[4 * BSTR]);
            }
#pragma unroll
            for (int i = 0; i < 4; i++)
#pragma unroll
                for (int j = 0; j < 4; j++)
                    mma8(acc[i][j], af[i], bf[j]);
        }
    }

    // epilogue
#pragma unroll
    for (int i = 0; i < 4; i++) {
        const int r0 = rowBase + wm + i * 16 + gid;
#pragma unroll
        for (int j = 0; j < 4; j++) {
            const int cn = colBase + wn + j * 8 + 2 * tg;   // col within fused N
            float v0 = acc[i][j][0], v1 = acc[i][j][1];
            float v2 = acc[i][j][2], v3 = acc[i][j][3];
            if (bias) {
                v0 += bias[cn]; v1 += bias[cn + 1];
                v2 += bias[cn]; v3 += bias[cn + 1];
            }
            if (cvtOut) {
                v0 = tf32f(v0); v1 = tf32f(v1); v2 = tf32f(v2); v3 = tf32f(v3);
            }
            float2 p0; p0.x = v0; p0.y = v1;
            float2 p1; p1.x = v2; p1.y = v3;
            *(float2*)(C + (size_t)r0 * ldc + colOff + cn) = p0;
            *(float2*)(C + (size_t)(r0 + 8) * ldc + colOff + cn) = p1;
        }
    }
}

// =====================================================================
// Elementwise kernels
// =====================================================================
// Concat [x | h_prev] -> g_xh (tf32-rounded)
__global__ void concat_xh_kernel(const float* __restrict__ x,
                                 const float* __restrict__ h,
                                 float* __restrict__ xh)
{
    int i = blockIdx.x * blockDim.x + threadIdx.x;   // float4 index
    if (i >= BDIM * 512) return;
    int b = i >> 9, c4 = i & 511;
    const float* src = (c4 < 256) ? (x + (size_t)b * 1024 + c4 * 4)
                                  : (h + (size_t)b * 1024 + (c4 - 256) * 4);
    float4 v = *(const float4*)src;
    v.x = tf32f(v.x); v.y = tf32f(v.y); v.z = tf32f(v.z); v.w = tf32f(v.w);
    *(float4*)(xh + (size_t)b * 2048 + c4 * 4) = v;
}

// LSTM gates: z (+bias) -> h, c ; h (tf32-rounded) into comb[:,0:U]
__global__ void lstm_gates_kernel(const float* __restrict__ z,
                                  const float* __restrict__ bias,
                                  const float* __restrict__ c_prev,
                                  float* __restrict__ out_h,
                                  float* __restrict__ out_c,
                                  float* __restrict__ comb)
{
    int i = blockIdx.x * blockDim.x + threadIdx.x;
    if (i >= BDIM * UDIM) return;
    int b = i / UDIM, u = i - b * UDIM;
    const float* zr = z + (size_t)b * 4 * UDIM;
    float zi = zr[u]            + bias[u];
    float zf = zr[UDIM + u]     + bias[UDIM + u];
    float zg = zr[2 * UDIM + u] + bias[2 * UDIM + u];
    float zo = zr[3 * UDIM + u] + bias[3 * UDIM + u];
    float si = 1.0f / (1.0f + expf(-zi));
    float sf = 1.0f / (1.0f + expf(-zf));
    float so = 1.0f / (1.0f + expf(-zo));
    float c = sf * c_prev[i] + si * tanhf(zg);
    float h = so * tanhf(c);
    out_h[i] = h;
    out_c[i] = c;
    comb[(size_t)b * NCOMB + u] = tf32f(h);
}

// silu(x) + cubic B-spline bases (tf32-rounded)
__device__ __forceinline__ float knot(int j) {
    return (float)(-1.0 + (2.0 / 5.0) * (double)(j - 3));
}
__global__ void act_kernel(const float* __restrict__ x, float* __restrict__ act)
{
    int i = blockIdx.x * blockDim.x + threadIdx.x;
    if (i >= BDIM * DDIM) return;
    int b = i / DDIM, d = i - b * DDIM;
    float xv = x[i];
    float s = xv / (1.0f + expf(-xv));

    float bb[11];
#pragma unroll
    for (int j = 0; j < 11; j++)
        bb[j] = (xv >= knot(j) && xv < knot(j + 1)) ? 1.0f : 0.0f;
#pragma unroll
    for (int p = 1; p <= 3; p++) {
#pragma unroll
        for (int j = 0; j <= 10 - p; j++) {
            float tj  = knot(j),     tjp  = knot(j + p);
            float tj1 = knot(j + 1), tjp1 = knot(j + p + 1);
            bb[j] = (xv - tj) / (tjp - tj) * bb[j]
                  + (tjp1 - xv) / (tjp1 - tj1) * bb[j + 1];
        }
    }
    float* row = act + (size_t)b * KACT;
    row[d] = tf32f(s);
    float* sp = row + DDIM + d * NB;
    float4 v0, v1;
    v0.x = tf32f(bb[0]); v0.y = tf32f(bb[1]); v0.z = tf32f(bb[2]); v0.w = tf32f(bb[3]);
    v1.x = tf32f(bb[4]); v1.y = tf32f(bb[5]); v1.z = tf32f(bb[6]); v1.w = tf32f(bb[7]);
    *(float4*)(sp + 0) = v0;
    *(float4*)(sp + 4) = v1;
}

// =====================================================================
// Launch
// =====================================================================
extern "C" void kernel_launch(void* const* d_in, const int* in_sizes, int n_in,
                              void* d_out, int out_size)
{
    const float* x       = (const float*)d_in[0];
    const float* h_prev  = (const float*)d_in[1];
    const float* c_prev  = (const float*)d_in[2];
    const float* lstm_k  = (const float*)d_in[3];   // [1024,4096]
    const float* lstm_rk = (const float*)d_in[4];   // [1024,4096]
    const float* lstm_b  = (const float*)d_in[5];   // [4096]
    const float* kan_bw  = (const float*)d_in[6];   // [3,1024,1024]
    const float* kan_sw  = (const float*)d_in[7];   // [3,8192,1024]
    const float* comb_w  = (const float*)d_in[8];   // [4096,1024]
    const float* comb_b  = (const float*)d_in[9];   // [1024]

    float* out   = (float*)d_out;
    float* out_h = out + (size_t)BDIM * UDIM;
    float* out_c = out + (size_t)2 * BDIM * UDIM;

    float *xh, *z, *act, *comb;
    cudaGetSymbolAddress((void**)&xh,   g_xh);
    cudaGetSymbolAddress((void**)&z,    g_z);
    cudaGetSymbolAddress((void**)&act,  g_act);
    cudaGetSymbolAddress((void**)&comb, g_comb);

    const int DYN = SSTG * STGB;   // 75776 bytes
    cudaFuncSetAttribute(gemm_mma, cudaFuncAttributeMaxDynamicSharedMemorySize, DYN);

    // 0) Concat A for LSTM (tf32)
    concat_xh_kernel<<<(BDIM * 512 + 255) / 256, 256>>>(x, h_prev, xh);

    // 1) Activations (silu + bases, tf32)
    act_kernel<<<(BDIM * DDIM + 255) / 256, 256>>>(x, act);

    // 2) LSTM GEMM: z = [x|h] @ [Wk;Wr]  -> [2048, 4096] (full fp32 out)
    gemm_mma<<<dim3(4096 / BN, BDIM / BM), 256, DYN>>>(
        xh, 2048,
        lstm_k, 0, lstm_rk, 0, 4096, 4096, 1024,
        nullptr, z, 4096, 0, 2048, 0);

    // 3) Gates -> h, c (h also into comb col 0..1023)
    lstm_gates_kernel<<<(BDIM * UDIM + 255) / 256, 256>>>(
        z, lstm_b, c_prev, out_h, out_c, comb);

    // 4) KAN (3 layers fused, N=3072): comb[:, 1024+n] (tf32 out)
    gemm_mma<<<dim3(3072 / BN, BDIM / BM), 256, DYN>>>(
        act, KACT,
        kan_bw, (long)1024 * 1024, kan_sw, (long)8192 * 1024,
        1024, 1024, 1024,
        nullptr, comb, NCOMB, 1024, KACT, 1);

    // 5) Combine: out = comb @ Wc + b -> [2048, 1024]
    gemm_mma<<<dim3(1024 / BN, BDIM / BM), 256, DYN>>>(
        comb, NCOMB,
        comb_w, 0, comb_w, 0, 1024, 1024, 4096,
        comb_b, out, 1024, 0, 4096, 0);
}

// round 4
// speedup vs baseline: 12.1289x; 2.3448x over previous
#include <cuda_runtime.h>
#include <cuda_fp16.h>
#include <cstdint>
#include <math.h>

// ---- Problem constants ----
#define BDIM 2048
#define DDIM 1024
#define UDIM 1024
#define NB   8
#define KACT 9216
#define NCOMB 4096

// ---- Scratch (device globals; no allocation allowed) ----
__device__ __half g_xh[BDIM * 2048];               // [x | h_prev] fp16
__device__ float  g_z[BDIM * 4096];                // LSTM preacts fp32
__device__ __half g_act[(size_t)BDIM * KACT];      // [silu | bases] fp16
__device__ __half g_comb[(size_t)BDIM * NCOMB];    // [h | kan0..2] fp16
__device__ __half g_wl[(size_t)2048 * 4096];       // fused [Wk;Wr]   K-rows x N
__device__ __half g_wk[(size_t)KACT * 3072];       // fused KAN weights
__device__ __half g_wc[(size_t)4096 * 1024];       // combine weights

// ---- PTX helpers ----
__device__ __forceinline__ uint32_t smem_u32(const void* p) {
    uint32_t a;
    asm("{ .reg .u64 t; cvta.to.shared.u64 t, %1; cvt.u32.u64 %0, t; }"
        : "=r"(a) : "l"(p));
    return a;
}
__device__ __forceinline__ void cp16(uint32_t s, const void* g) {
    asm volatile("cp.async.cg.shared.global [%0], [%1], 16;" :: "r"(s), "l"(g));
}
__device__ __forceinline__ void cp_commit() {
    asm volatile("cp.async.commit_group;" ::: "memory");
}
template<int N> __device__ __forceinline__ void cp_wait() {
    asm volatile("cp.async.wait_group %0;" :: "n"(N) : "memory");
}
__device__ __forceinline__ void ldmA(uint32_t* r, uint32_t a) {
    asm volatile("ldmatrix.sync.aligned.m8n8.x4.shared.b16 {%0,%1,%2,%3}, [%4];"
                 : "=r"(r[0]), "=r"(r[1]), "=r"(r[2]), "=r"(r[3]) : "r"(a));
}
__device__ __forceinline__ void ldmBT(uint32_t* r, uint32_t a) {
    asm volatile("ldmatrix.sync.aligned.m8n8.x4.trans.shared.b16 {%0,%1,%2,%3}, [%4];"
                 : "=r"(r[0]), "=r"(r[1]), "=r"(r[2]), "=r"(r[3]) : "r"(a));
}
__device__ __forceinline__ void mma16(float* c, const uint32_t* a, const uint32_t* b) {
    asm volatile(
        "mma.sync.aligned.m16n8k16.row.col.f32.f16.f16.f32 "
        "{%0,%1,%2,%3}, {%4,%5,%6,%7}, {%8,%9}, {%0,%1,%2,%3};"
        : "+f"(c[0]), "+f"(c[1]), "+f"(c[2]), "+f"(c[3])
        : "r"(a[0]), "r"(a[1]), "r"(a[2]), "r"(a[3]), "r"(b[0]), "r"(b[1]));
}

// =====================================================================
// FP16 mma.sync GEMM: C[m, colOff+n] = sum_k A[m,k]*B[k,n] (+bias)
// A: [M,K] fp16 row-major. B: [K,N] fp16 row-major (pre-fused/converted).
// BM=128, BN=128, BK=64, 3-stage cp.async, 8 warps, 64x32/warp.
// COUT: 0 = fp32 C, 1 = fp16 C.
// =====================================================================
#define BKH 64
#define HAB 16384              // A tile bytes: 128 rows * 128B
#define HSTG 32768             // A + B per stage
#define HSSTG 3

extern __shared__ char smem_h[];

// A smem: row r (0..127), 16B-chunk c (0..7):  r*128 + (c ^ (r&7))*16
// B smem: row k (0..63),  16B-chunk c (0..15): k*256 + (c ^ (k&7))*16
__device__ __forceinline__ uint32_t offA(int r, int c) {
    return (uint32_t)(r * 128 + ((c ^ (r & 7)) << 4));
}
__device__ __forceinline__ uint32_t offB(int k, int c) {
    return (uint32_t)(k * 256 + ((c ^ (k & 7)) << 4));
}

template<int COUT>
__global__ __launch_bounds__(256, 2) void gemm_h(
    const __half* __restrict__ A, int lda,
    const __half* __restrict__ B, int ldb,
    const float* __restrict__ bias,
    void* __restrict__ Cv, int ldc, int colOff, int K)
{
    const int tid = threadIdx.x;
    const int lane = tid & 31;
    const int w = tid >> 5;
    const int rowBase = blockIdx.y * 128;
    const int colBase = blockIdx.x * 128;

    const uint32_t sb = smem_u32(smem_h);

    float acc[4][4][4];
#pragma unroll
    for (int i = 0; i < 4; i++)
#pragma unroll
        for (int j = 0; j < 4; j++)
#pragma unroll
            for (int q = 0; q < 4; q++) acc[i][j][q] = 0.0f;

    const int nk = K / BKH;

    auto load_stage = [&](int t, int s) {
        const int kBase = t * BKH;
        const uint32_t sA = sb + s * HSTG;
        const uint32_t sB = sA + HAB;
#pragma unroll
        for (int i = 0; i < 4; i++) {               // A: 1024 chunks / 256 thr
            int idx = i * 256 + tid;
            int r = idx >> 3, c = idx & 7;
            cp16(sA + offA(r, c), A + (size_t)(rowBase + r) * lda + kBase + c * 8);
        }
#pragma unroll
        for (int i = 0; i < 4; i++) {               // B: 1024 chunks / 256 thr
            int idx = i * 256 + tid;
            int r = idx >> 4, c = idx & 15;
            cp16(sB + offB(r, c), B + (size_t)(kBase + r) * ldb + colBase + c * 8);
        }
    };

#pragma unroll
    for (int s = 0; s < HSSTG - 1; s++) { load_stage(s, s); cp_commit(); }

    const int wm = (w >> 2) * 64;
    const int wn = (w & 3) * 32;
    const int gid = lane >> 2;
    const int tg  = lane & 3;
    const int aRow = lane & 15;          // row within 16-row tile
    const int aSel = lane >> 4;          // chunk select
    const int bRow = lane & 15;          // k within k16
    const int bSel = lane >> 4;          // n-chunk select

    for (int t = 0; t < nk; t++) {
        cp_wait<HSSTG - 2>();
        __syncthreads();
        const int tn = t + HSSTG - 1;
        if (tn < nk) load_stage(tn, tn % HSSTG);
        cp_commit();

        const uint32_t sA = sb + (t % HSSTG) * HSTG;
        const uint32_t sB = sA + HAB;

#pragma unroll
        for (int ks = 0; ks < 4; ks++) {
            uint32_t af[4][4], bf[4][2];
#pragma unroll
            for (int i = 0; i < 4; i++)
                ldmA(af[i], sA + offA(wm + i * 16 + aRow, 2 * ks + aSel));
#pragma unroll
            for (int j2 = 0; j2 < 2; j2++) {
                uint32_t r4[4];
                ldmBT(r4, sB + offB(ks * 16 + bRow, (w & 3) * 4 + j2 * 2 + bSel));
                bf[2 * j2][0] = r4[0]; bf[2 * j2][1] = r4[1];
                bf[2 * j2 + 1][0] = r4[2]; bf[2 * j2 + 1][1] = r4[3];
            }
#pragma unroll
            for (int i = 0; i < 4; i++)
#pragma unroll
                for (int j = 0; j < 4; j++)
                    mma16(acc[i][j], af[i], bf[j]);
        }
    }

    // epilogue
#pragma unroll
    for (int i = 0; i < 4; i++) {
        const int r0 = rowBase + wm + i * 16 + gid;
#pragma unroll
        for (int j = 0; j < 4; j++) {
            const int cn = colBase + wn + j * 8 + 2 * tg;
            float v0 = acc[i][j][0], v1 = acc[i][j][1];
            float v2 = acc[i][j][2], v3 = acc[i][j][3];
            if (bias) {
                v0 += bias[cn]; v1 += bias[cn + 1];
                v2 += bias[cn]; v3 += bias[cn + 1];
            }
            if (COUT == 0) {
                float* C = (float*)Cv;
                float2 p0; p0.x = v0; p0.y = v1;
                float2 p1; p1.x = v2; p1.y = v3;
                *(float2*)(C + (size_t)r0 * ldc + colOff + cn) = p0;
                *(float2*)(C + (size_t)(r0 + 8) * ldc + colOff + cn) = p1;
            } else {
                __half* C = (__half*)Cv;
                *(__half2*)(C + (size_t)r0 * ldc + colOff + cn) = __floats2half2_rn(v0, v1);
                *(__half2*)(C + (size_t)(r0 + 8) * ldc + colOff + cn) = __floats2half2_rn(v2, v3);
            }
        }
    }
}

// =====================================================================
// Weight conversion (fp32 -> fp16, pre-fused layouts)
// =====================================================================
__global__ void cvt_lstm(const float* __restrict__ wk, const float* __restrict__ wr,
                         __half* __restrict__ o)
{
    int i = blockIdx.x * 256 + threadIdx.x;      // per 4 elems
    long e = (long)i * 4;
    int r = (int)(e >> 12), n = (int)(e & 4095);
    const float* s = (r < 1024) ? wk + (size_t)r * 4096 + n
                                : wr + (size_t)(r - 1024) * 4096 + n;
    float4 v = *(const float4*)s;
    *(__half2*)(o + e)     = __floats2half2_rn(v.x, v.y);
    *(__half2*)(o + e + 2) = __floats2half2_rn(v.z, v.w);
}

__global__ void cvt_kan(const float* __restrict__ bw, const float* __restrict__ sw,
                        __half* __restrict__ o)
{
    int col = (blockIdx.x * 256 + threadIdx.x) * 4;   // 0..3068
    int k = blockIdx.y;                                // 0..9215
    int l = col >> 10, u = col & 1023;
    const float* s = (k < 1024)
        ? bw + ((size_t)l * 1024 + k) * 1024 + u
        : sw + ((size_t)l * 8192 + (k - 1024)) * 1024 + u;
    float4 v = *(const float4*)s;
    __half* d = o + (size_t)k * 3072 + col;
    *(__half2*)(d)     = __floats2half2_rn(v.x, v.y);
    *(__half2*)(d + 2) = __floats2half2_rn(v.z, v.w);
}

__global__ void cvt_comb(const float* __restrict__ wc, __half* __restrict__ o)
{
    int i = blockIdx.x * 256 + threadIdx.x;
    long e = (long)i * 4;
    float4 v = *(const float4*)(wc + e);
    *(__half2*)(o + e)     = __floats2half2_rn(v.x, v.y);
    *(__half2*)(o + e + 2) = __floats2half2_rn(v.z, v.w);
}

// =====================================================================
// Elementwise producers (fp16 outputs)
// =====================================================================
__global__ void concat_xh_kernel(const float* __restrict__ x,
                                 const float* __restrict__ h,
                                 __half* __restrict__ xh)
{
    int i = blockIdx.x * 256 + threadIdx.x;      // per 8 elems
    long e = (long)i * 8;
    int b = (int)(e >> 11), c = (int)(e & 2047);
    const float* src = (c < 1024) ? x + (size_t)b * 1024 + c
                                  : h + (size_t)b * 1024 + (c - 1024);
    float4 v0 = *(const float4*)src;
    float4 v1 = *(const float4*)(src + 4);
    __half2 o[4];
    o[0] = __floats2half2_rn(v0.x, v0.y);
    o[1] = __floats2half2_rn(v0.z, v0.w);
    o[2] = __floats2half2_rn(v1.x, v1.y);
    o[3] = __floats2half2_rn(v1.z, v1.w);
    *(uint4*)(xh + e) = *(uint4*)o;
}

__global__ void lstm_gates_kernel(const float* __restrict__ z,
                                  const float* __restrict__ bias,
                                  const float* __restrict__ c_prev,
                                  float* __restrict__ out_h,
                                  float* __restrict__ out_c,
                                  __half* __restrict__ comb)
{
    int i = blockIdx.x * blockDim.x + threadIdx.x;
    if (i >= BDIM * UDIM) return;
    int b = i / UDIM, u = i - b * UDIM;
    const float* zr = z + (size_t)b * 4 * UDIM;
    float zi = zr[u]            + bias[u];
    float zf = zr[UDIM + u]     + bias[UDIM + u];
    float zg = zr[2 * UDIM + u] + bias[2 * UDIM + u];
    float zo = zr[3 * UDIM + u] + bias[3 * UDIM + u];
    float si = 1.0f / (1.0f + expf(-zi));
    float sf = 1.0f / (1.0f + expf(-zf));
    float so = 1.0f / (1.0f + expf(-zo));
    float c = sf * c_prev[i] + si * tanhf(zg);
    float h = so * tanhf(c);
    out_h[i] = h;
    out_c[i] = c;
    comb[(size_t)b * NCOMB + u] = __float2half(h);
}

__device__ __forceinline__ float knot(int j) {
    return (float)(-1.0 + (2.0 / 5.0) * (double)(j - 3));
}
__global__ void act_kernel(const float* __restrict__ x, __half* __restrict__ act)
{
    int i = blockIdx.x * blockDim.x + threadIdx.x;
    if (i >= BDIM * DDIM) return;
    int b = i / DDIM, d = i - b * DDIM;
    float xv = x[i];
    float s = xv / (1.0f + expf(-xv));

    float bb[11];
#pragma unroll
    for (int j = 0; j < 11; j++)
        bb[j] = (xv >= knot(j) && xv < knot(j + 1)) ? 1.0f : 0.0f;
#pragma unroll
    for (int p = 1; p <= 3; p++) {
#pragma unroll
        for (int j = 0; j <= 10 - p; j++) {
            float tj  = knot(j),     tjp  = knot(j + p);
            float tj1 = knot(j + 1), tjp1 = knot(j + p + 1);
            bb[j] = (xv - tj) / (tjp - tj) * bb[j]
                  + (tjp1 - xv) / (tjp1 - tj1) * bb[j + 1];
        }
    }
    __half* row = act + (size_t)b * KACT;
    row[d] = __float2half(s);
    __half2 o[4];
    o[0] = __floats2half2_rn(bb[0], bb[1]);
    o[1] = __floats2half2_rn(bb[2], bb[3]);
    o[2] = __floats2half2_rn(bb[4], bb[5]);
    o[3] = __floats2half2_rn(bb[6], bb[7]);
    *(uint4*)(row + DDIM + d * NB) = *(uint4*)o;
}

// =====================================================================
// Launch
// =====================================================================
extern "C" void kernel_launch(void* const* d_in, const int* in_sizes, int n_in,
                              void* d_out, int out_size)
{
    const float* x       = (const float*)d_in[0];
    const float* h_prev  = (const float*)d_in[1];
    const float* c_prev  = (const float*)d_in[2];
    const float* lstm_k  = (const float*)d_in[3];
    const float* lstm_rk = (const float*)d_in[4];
    const float* lstm_b  = (const float*)d_in[5];
    const float* kan_bw  = (const float*)d_in[6];
    const float* kan_sw  = (const float*)d_in[7];
    const float* comb_w  = (const float*)d_in[8];
    const float* comb_b  = (const float*)d_in[9];

    float* out   = (float*)d_out;
    float* out_h = out + (size_t)BDIM * UDIM;
    float* out_c = out + (size_t)2 * BDIM * UDIM;

    __half *xh, *act, *comb, *wl, *wk, *wc;
    float* z;
    cudaGetSymbolAddress((void**)&xh,   g_xh);
    cudaGetSymbolAddress((void**)&z,    g_z);
    cudaGetSymbolAddress((void**)&act,  g_act);
    cudaGetSymbolAddress((void**)&comb, g_comb);
    cudaGetSymbolAddress((void**)&wl,   g_wl);
    cudaGetSymbolAddress((void**)&wk,   g_wk);
    cudaGetSymbolAddress((void**)&wc,   g_wc);

    const int DYN = HSSTG * HSTG;   // 98304
    cudaFuncSetAttribute(gemm_h<0>, cudaFuncAttributeMaxDynamicSharedMemorySize, DYN);
    cudaFuncSetAttribute(gemm_h<1>, cudaFuncAttributeMaxDynamicSharedMemorySize, DYN);

    // Weight conversion / fusion
    cvt_lstm<<<2048 * 4096 / 4 / 256, 256>>>(lstm_k, lstm_rk, wl);
    cvt_kan<<<dim3(3, KACT), 256>>>(kan_bw, kan_sw, wk);
    cvt_comb<<<4096 * 1024 / 4 / 256, 256>>>(comb_w, wc);

    // Activation producers
    concat_xh_kernel<<<BDIM * 2048 / 8 / 256, 256>>>(x, h_prev, xh);
    act_kernel<<<(BDIM * DDIM + 255) / 256, 256>>>(x, act);

    // LSTM GEMM: z = [x|h] @ [Wk;Wr]  (fp32 out)
    gemm_h<0><<<dim3(4096 / 128, BDIM / 128), 256, DYN>>>(
        xh, 2048, wl, 4096, nullptr, z, 4096, 0, 2048);

    // Gates
    lstm_gates_kernel<<<(BDIM * UDIM + 255) / 256, 256>>>(
        z, lstm_b, c_prev, out_h, out_c, comb);

    // KAN (3 layers fused, N=3072) -> comb[:, 1024+n] (fp16 out)
    gemm_h<1><<<dim3(3072 / 128, BDIM / 128), 256, DYN>>>(
        act, KACT, wk, 3072, nullptr, comb, NCOMB, 1024, KACT);

    // Combine: out = comb @ Wc + b (fp32 out)
    gemm_h<0><<<dim3(1024 / 128, BDIM / 128), 256, DYN>>>(
        comb, NCOMB, wc, 1024, comb_b, out, 1024, 0, 4096);
}